// round 2
// baseline (speedup 1.0000x reference)
#include <cuda_runtime.h>

#define NANCH 8400
#define BATCH 32
#define NCLS  80
#define BINS  16
#define LOG2E 1.44269504f

// [0]=cls_sum [1]=iou_sum [2]=dfl_sum [3]=pos_count
__device__ double g_acc[4];
__device__ unsigned int g_done;

// focal-loss element for target=0: -0.75 * sigmoid(s)^2 * ln(sigmoid(-s))
__device__ __forceinline__ float cls_neg(float s) {
    float e   = exp2f(s * LOG2E);            // e^s  (1 MUFU + 1 FMUL)
    e = fminf(e, 1e30f);
    float u   = __fdividef(1.f, 1.f + e);    // sigmoid(-s)  (1 MUFU + ops)
    float lnu = __logf(u);                   // ln u         (1 MUFU + 1 FMUL)
    float omp = 1.f - u;                     // sigmoid(s)
    return -0.75f * omp * omp * lnu;
}

__global__ void __launch_bounds__(128) yolo_loss_kernel(
    const float* __restrict__ p0, const float* __restrict__ p1, const float* __restrict__ p2,
    const float* __restrict__ gtb, const int* __restrict__ gtl, const int* __restrict__ mind,
    float* __restrict__ out, int out_n)
{
    const int v = blockIdx.x * 128 + threadIdx.x;   // one thread = 4 consecutive anchors
    float cls_s = 0.f, iou_s = 0.f, dfl_s = 0.f;
    int cnt = 0;

    {
        int b = v / 2100;                // 2100 quads per image
        int q = v - b * 2100;
        int a = q << 2;                  // anchor base, multiple of 4

        const float* p; int HW, hw, W; float stride, rstride;
        if (a < 6400)      { p = p0; HW = 6400; hw = a;        W = 80; stride = 8.f;  rstride = 0.125f;   }
        else if (a < 8000) { p = p1; HW = 1600; hw = a - 6400; W = 40; stride = 16.f; rstride = 0.0625f;  }
        else               { p = p2; HW = 400;  hw = a - 8000; W = 20; stride = 32.f; rstride = 0.03125f; }

        const float* base = p + (size_t)b * 144 * HW + hw;   // 16B aligned (hw % 4 == 0)
        const int4 mi = *reinterpret_cast<const int4*>(mind + b * NANCH + a);

        // ---------- classification (all anchors, t=0 formula everywhere) ----------
        #pragma unroll 4
        for (int c = 0; c < NCLS; ++c) {
            float4 s4 = *reinterpret_cast<const float4*>(base + (size_t)(64 + c) * HW);
            cls_s += cls_neg(s4.x);
            cls_s += cls_neg(s4.y);
            cls_s += cls_neg(s4.z);
            cls_s += cls_neg(s4.w);
        }

        // ---------- positives: label correction + DFL + IoU (~5% of anchors) ----------
        int inds[4] = { mi.x, mi.y, mi.z, mi.w };
        #pragma unroll
        for (int j = 0; j < 4; ++j) {
            int ind = inds[j];
            if (ind < 0) continue;
            cnt++;
            int lbl = gtl[b * 32 + ind];

            // replace t=0 term with t=1 term on the label channel (reload: L1/L2 hit)
            {
                float s = base[j + (size_t)(64 + lbl) * HW];
                float e = exp2f(s * LOG2E); e = fminf(e, 1e30f);
                float u = __fdividef(1.f, 1.f + e);
                float omp = 1.f - u;
                float elem0 = -0.75f * omp * omp * __logf(u);
                float elem1 = -0.25f * u * u * __logf(fmaxf(omp, 1e-12f));
                cls_s += elem1 - elem0;
            }

            const float* tb4 = gtb + (size_t)(b * 32 + ind) * 4;
            float tx1 = tb4[0], ty1 = tb4[1], tx2 = tb4[2], ty2 = tb4[3];

            int hwj = hw + j;
            int wy = hwj / W, wx = hwj - wy * W;
            float gx = (wx + 0.5f) * stride;
            float gy = (wy + 0.5f) * stride;

            float tgt[4] = { fmaxf(gx - tx1, 0.f), fmaxf(gy - ty1, 0.f),
                             fmaxf(tx2 - gx, 0.f), fmaxf(ty2 - gy, 0.f) };
            float d[4];

            #pragma unroll
            for (int k = 0; k < 4; ++k) {
                float vv[BINS];
                float m = -1e30f;
                #pragma unroll
                for (int jj = 0; jj < BINS; ++jj) {
                    vv[jj] = base[j + (size_t)(k * BINS + jj) * HW];
                    m = fmaxf(m, vv[jj]);
                }
                float S = 0.f, E = 0.f;
                #pragma unroll
                for (int jj = 0; jj < BINS; ++jj) {
                    float ee = __expf(vv[jj] - m);
                    S += ee;
                    E += ee * (float)jj;
                }
                d[k] = __fdividef(E, S) * stride;

                float tb = fminf(tgt[k] * rstride, 15.f - 1e-6f);
                int   lo = (int)tb;
                int   hi = min(lo + 1, BINS - 1);
                float aa = tb - (float)lo;
                float vlo = vv[0], vhi = vv[0];
                #pragma unroll
                for (int jj = 1; jj < BINS; ++jj) {      // register-select (avoid local mem)
                    vlo = (jj == lo) ? vv[jj] : vlo;
                    vhi = (jj == hi) ? vv[jj] : vhi;
                }
                float lS = __logf(S);
                dfl_s -= (1.f - aa) * (vlo - m - lS) + aa * (vhi - m - lS);
            }

            float px1 = gx - d[0], py1 = gy - d[1];
            float px2 = gx + d[2], py2 = gy + d[3];
            float ix1 = fmaxf(px1, tx1), iy1 = fmaxf(py1, ty1);
            float ix2 = fminf(px2, tx2), iy2 = fminf(py2, ty2);
            float inter  = fmaxf(ix2 - ix1, 0.f) * fmaxf(iy2 - iy1, 0.f);
            float area_p = fmaxf(px2 - px1, 0.f) * fmaxf(py2 - py1, 0.f);
            float area_t = fmaxf(tx2 - tx1, 0.f) * fmaxf(ty2 - ty1, 0.f);
            float iou = inter / (area_p + area_t - inter + 1e-7f);
            iou_s += 1.f - iou;
        }
    }

    // ---------- block reduction: warp shuffle -> shared -> global double atomics ----------
    #pragma unroll
    for (int o = 16; o > 0; o >>= 1) {
        cls_s += __shfl_down_sync(0xffffffffu, cls_s, o);
        iou_s += __shfl_down_sync(0xffffffffu, iou_s, o);
        dfl_s += __shfl_down_sync(0xffffffffu, dfl_s, o);
        cnt   += __shfl_down_sync(0xffffffffu, cnt,   o);
    }

    __shared__ float sc[4], si[4], sd[4];
    __shared__ int   sp[4];
    int lane = threadIdx.x & 31;
    int warp = threadIdx.x >> 5;
    if (lane == 0) { sc[warp] = cls_s; si[warp] = iou_s; sd[warp] = dfl_s; sp[warp] = cnt; }
    __syncthreads();

    if (warp == 0 && lane == 0) {
        cls_s = sc[0] + sc[1] + sc[2] + sc[3];
        iou_s = si[0] + si[1] + si[2] + si[3];
        dfl_s = sd[0] + sd[1] + sd[2] + sd[3];
        cnt   = sp[0] + sp[1] + sp[2] + sp[3];

        atomicAdd(&g_acc[0], (double)cls_s);
        atomicAdd(&g_acc[1], (double)iou_s);
        atomicAdd(&g_acc[2], (double)dfl_s);
        atomicAdd(&g_acc[3], (double)cnt);

        __threadfence();
        unsigned int ticket = atomicAdd(&g_done, 1u);
        if (ticket == gridDim.x - 1) {
            // last block: finalize, write output, reset state for next replay
            double c0 = atomicAdd(&g_acc[0], 0.0);
            double c1 = atomicAdd(&g_acc[1], 0.0);
            double c2 = atomicAdd(&g_acc[2], 0.0);
            double c3 = atomicAdd(&g_acc[3], 0.0);
            double np = c3 < 1.0 ? 1.0 : c3;
            double total = c0 / np + 7.5 * c1 / np + 1.5 * c2 / (np * 4.0);
            for (int i = 0; i < out_n; ++i) out[i] = (float)total;
            g_acc[0] = 0.0; g_acc[1] = 0.0; g_acc[2] = 0.0; g_acc[3] = 0.0;
            __threadfence();
            g_done = 0u;
        }
    }
}

extern "C" void kernel_launch(void* const* d_in, const int* in_sizes, int n_in,
                              void* d_out, int out_size) {
    const float* p0   = (const float*)d_in[0];
    const float* p1   = (const float*)d_in[1];
    const float* p2   = (const float*)d_in[2];
    const float* gtb  = (const float*)d_in[3];
    const int*   gtl  = (const int*)d_in[4];
    const int*   mind = (const int*)d_in[5];
    float* out = (float*)d_out;

    const int total_quads = BATCH * NANCH / 4;   // 67200
    const int threads = 128;
    const int blocks = total_quads / threads;    // 525 exactly

    yolo_loss_kernel<<<blocks, threads>>>(p0, p1, p2, gtb, gtl, mind, out, out_size);
}

// round 3
// speedup vs baseline: 1.9709x; 1.9709x over previous
#include <cuda_runtime.h>

#define NANCH 8400
#define BATCH 32
#define NCLS  80
#define BINS  16
#define LOG2E 1.44269504f

// [0]=cls_sum [1]=iou_sum [2]=dfl_sum [3]=pos_count
__device__ double g_acc[4];
__device__ unsigned int g_done;

// focal-loss element for target=0: -0.75 * sigmoid(s)^2 * ln(sigmoid(-s))
// 3 MUFU (EX2, RCP, LG2) + ~7 fma-pipe ops
__device__ __forceinline__ float cls_neg(float s) {
    float e   = __expf(s);                  // e^s
    float u   = __fdividef(1.f, 1.f + e);   // sigmoid(-s)
    float lnu = __logf(u);                  // ln u
    float p   = 1.f - u;                    // sigmoid(s)
    return -0.75f * p * p * lnu;
}

__global__ void __launch_bounds__(256, 5) yolo_loss_kernel(
    const float* __restrict__ p0, const float* __restrict__ p1, const float* __restrict__ p2,
    const float* __restrict__ gtb, const int* __restrict__ gtl, const int* __restrict__ mind,
    float* __restrict__ out, int out_n)
{
    const int g = blockIdx.x * 256 + threadIdx.x;   // one thread = one (b, anchor)
    float cls_s = 0.f, iou_s = 0.f, dfl_s = 0.f;
    int cnt = 0;

    if (g < BATCH * NANCH) {
        int b = g / NANCH;
        int a = g - b * NANCH;

        const float* p; int HW, hw, W; float stride, rstride;
        if (a < 6400)      { p = p0; HW = 6400; hw = a;        W = 80; stride = 8.f;  rstride = 0.125f;   }
        else if (a < 8000) { p = p1; HW = 1600; hw = a - 6400; W = 40; stride = 16.f; rstride = 0.0625f;  }
        else               { p = p2; HW = 400;  hw = a - 8000; W = 20; stride = 32.f; rstride = 0.03125f; }

        const float* base = p + (size_t)b * 144 * HW + hw;
        const float* cbase = base + (size_t)64 * HW;

        // ---------- classification: t=0 formula on all 80 channels ----------
        float c0 = 0.f, c1 = 0.f, c2 = 0.f, c3 = 0.f;
        #pragma unroll
        for (int c = 0; c < NCLS; c += 4) {
            float s0 = cbase[(size_t)(c + 0) * HW];
            float s1 = cbase[(size_t)(c + 1) * HW];
            float s2 = cbase[(size_t)(c + 2) * HW];
            float s3 = cbase[(size_t)(c + 3) * HW];
            c0 += cls_neg(s0);
            c1 += cls_neg(s1);
            c2 += cls_neg(s2);
            c3 += cls_neg(s3);
        }
        cls_s = (c0 + c1) + (c2 + c3);

        // ---------- positives only: label fixup + DFL + IoU (~5% of anchors) ----------
        int ind = mind[g];
        if (ind >= 0) {
            cnt = 1;
            int lbl = gtl[b * 32 + ind];

            // swap t=0 -> t=1 on the label channel (reload hits L1/L2)
            {
                float s = cbase[(size_t)lbl * HW];
                float e = __expf(s);
                float u = __fdividef(1.f, 1.f + e);
                float pp = 1.f - u;
                float elem0 = -0.75f * pp * pp * __logf(u);
                float elem1 = -0.25f * u * u * __logf(fmaxf(pp, 1e-12f));
                cls_s += elem1 - elem0;
            }

            const float* tb4 = gtb + (size_t)(b * 32 + ind) * 4;
            float tx1 = tb4[0], ty1 = tb4[1], tx2 = tb4[2], ty2 = tb4[3];

            int wy = hw / W, wx = hw - wy * W;
            float gx = (wx + 0.5f) * stride;
            float gy = (wy + 0.5f) * stride;

            float tgt[4] = { fmaxf(gx - tx1, 0.f), fmaxf(gy - ty1, 0.f),
                             fmaxf(tx2 - gx, 0.f), fmaxf(ty2 - gy, 0.f) };
            float d[4];

            #pragma unroll
            for (int k = 0; k < 4; ++k) {
                float tb = fminf(tgt[k] * rstride, 15.f - 1e-6f);
                int   lo = (int)tb;
                int   hi = min(lo + 1, BINS - 1);
                float aa = tb - (float)lo;

                // single pass, no max-subtraction (|v| <~ 6, exp is safe)
                float S = 0.f, E = 0.f, vlo = 0.f, vhi = 0.f;
                #pragma unroll
                for (int j = 0; j < BINS; ++j) {
                    float v = base[(size_t)(k * BINS + j) * HW];
                    float e = __expf(v);
                    S += e;
                    E += e * (float)j;
                    vlo = (j == lo) ? v : vlo;
                    vhi = (j == hi) ? v : vhi;
                }
                d[k] = __fdividef(E, S) * stride;
                float lS = __logf(S);
                dfl_s -= (1.f - aa) * (vlo - lS) + aa * (vhi - lS);
            }

            float px1 = gx - d[0], py1 = gy - d[1];
            float px2 = gx + d[2], py2 = gy + d[3];
            float ix1 = fmaxf(px1, tx1), iy1 = fmaxf(py1, ty1);
            float ix2 = fminf(px2, tx2), iy2 = fminf(py2, ty2);
            float inter  = fmaxf(ix2 - ix1, 0.f) * fmaxf(iy2 - iy1, 0.f);
            float area_p = fmaxf(px2 - px1, 0.f) * fmaxf(py2 - py1, 0.f);
            float area_t = fmaxf(tx2 - tx1, 0.f) * fmaxf(ty2 - ty1, 0.f);
            float iou = inter / (area_p + area_t - inter + 1e-7f);
            iou_s = 1.f - iou;
        }
    }

    // ---------- block reduction: warp shuffle -> shared -> global double atomics ----------
    #pragma unroll
    for (int o = 16; o > 0; o >>= 1) {
        cls_s += __shfl_down_sync(0xffffffffu, cls_s, o);
        iou_s += __shfl_down_sync(0xffffffffu, iou_s, o);
        dfl_s += __shfl_down_sync(0xffffffffu, dfl_s, o);
        cnt   += __shfl_down_sync(0xffffffffu, cnt,   o);
    }

    __shared__ float sc[8], si[8], sd[8];
    __shared__ int   sp[8];
    int lane = threadIdx.x & 31;
    int warp = threadIdx.x >> 5;
    if (lane == 0) { sc[warp] = cls_s; si[warp] = iou_s; sd[warp] = dfl_s; sp[warp] = cnt; }
    __syncthreads();

    if (warp == 0 && lane == 0) {
        cls_s = 0.f; iou_s = 0.f; dfl_s = 0.f; cnt = 0;
        #pragma unroll
        for (int w = 0; w < 8; ++w) {
            cls_s += sc[w]; iou_s += si[w]; dfl_s += sd[w]; cnt += sp[w];
        }

        atomicAdd(&g_acc[0], (double)cls_s);
        atomicAdd(&g_acc[1], (double)iou_s);
        atomicAdd(&g_acc[2], (double)dfl_s);
        atomicAdd(&g_acc[3], (double)cnt);

        __threadfence();
        unsigned int ticket = atomicAdd(&g_done, 1u);
        if (ticket == gridDim.x - 1) {
            double v0 = atomicAdd(&g_acc[0], 0.0);
            double v1 = atomicAdd(&g_acc[1], 0.0);
            double v2 = atomicAdd(&g_acc[2], 0.0);
            double v3 = atomicAdd(&g_acc[3], 0.0);
            double np = v3 < 1.0 ? 1.0 : v3;
            double total = v0 / np + 7.5 * v1 / np + 1.5 * v2 / (np * 4.0);
            for (int i = 0; i < out_n; ++i) out[i] = (float)total;
            g_acc[0] = 0.0; g_acc[1] = 0.0; g_acc[2] = 0.0; g_acc[3] = 0.0;
            __threadfence();
            g_done = 0u;
        }
    }
}

extern "C" void kernel_launch(void* const* d_in, const int* in_sizes, int n_in,
                              void* d_out, int out_size) {
    const float* p0   = (const float*)d_in[0];
    const float* p1   = (const float*)d_in[1];
    const float* p2   = (const float*)d_in[2];
    const float* gtb  = (const float*)d_in[3];
    const int*   gtl  = (const int*)d_in[4];
    const int*   mind = (const int*)d_in[5];
    float* out = (float*)d_out;

    const int total = BATCH * NANCH;              // 268800
    const int threads = 256;
    const int blocks = (total + threads - 1) / threads;  // 1050

    yolo_loss_kernel<<<blocks, threads>>>(p0, p1, p2, gtb, gtl, mind, out, out_size);
}